// round 1
// baseline (speedup 1.0000x reference)
#include <cuda_runtime.h>

// Problem constants
#define BB   8
#define CC   256
#define HH   64
#define WWW  64
#define HWSZ 4096      // HH*WWW
#define K2C  9
#define OO   256

// Scratch (device globals — no allocation allowed)
__device__ float  g_xT[BB * HWSZ * CC];          // x transposed: [B][HW][C]  (32 MB)
__device__ float  g_Wt[K2C * CC * OO];           // weight transposed: [k2][c][o] (2.25 MB)
__device__ int4   g_idx[BB * K2C * HWSZ];        // 4 clamped corner spatial indices
__device__ float4 g_wgt[BB * K2C * HWSZ];        // 4 bilinear weights (zeroed if OOB)

// ---------------------------------------------------------------------------
// Kernel A: transpose x [B][C][HW] -> g_xT [B][HW][C]
// ---------------------------------------------------------------------------
__global__ void transpose_x_kernel(const float* __restrict__ x) {
    __shared__ __align__(16) float tile[32][33];
    int b   = blockIdx.z;
    int hw0 = blockIdx.x * 32;
    int c0  = blockIdx.y * 32;
    int tx = threadIdx.x;      // 0..31
    int ty = threadIdx.y;      // 0..7
    const float* xb = x + (size_t)b * CC * HWSZ;
#pragma unroll
    for (int i = 0; i < 4; i++) {
        int c = c0 + ty + i * 8;
        tile[ty + i * 8][tx] = xb[(size_t)c * HWSZ + hw0 + tx];
    }
    __syncthreads();
    float* xt = g_xT + (size_t)b * HWSZ * CC;
#pragma unroll
    for (int i = 0; i < 4; i++) {
        int hw = hw0 + ty + i * 8;
        xt[(size_t)hw * CC + c0 + tx] = tile[tx][ty + i * 8];
    }
}

// ---------------------------------------------------------------------------
// Kernel B: build bilinear meta (4 corner indices + 4 weights) per (b,k2,p)
// ---------------------------------------------------------------------------
__device__ __forceinline__ int clamp63(int v) {
    return v < 0 ? 0 : (v > 63 ? 63 : v);
}

__global__ void build_meta_kernel(const float* __restrict__ offset) {
    int t = blockIdx.x * blockDim.x + threadIdx.x;   // < B*K2*HW
    int p  = t & (HWSZ - 1);
    int bk = t >> 12;
    int k2 = bk % K2C;
    int b  = bk / K2C;
    int ho = p >> 6;
    int wo = p & 63;
    int ky = k2 / 3;
    int kx = k2 % 3;
    const float* ob = offset + (size_t)b * 2 * K2C * HWSZ;
    float dy = ob[(size_t)(k2 * 2 + 0) * HWSZ + p];
    float dx = ob[(size_t)(k2 * 2 + 1) * HWSZ + p];
    float py = (float)(ho - 1 + ky) + dy;
    float px = (float)(wo - 1 + kx) + dx;
    float y0f = floorf(py);
    float x0f = floorf(px);
    int   y0  = (int)y0f;
    int   x0  = (int)x0f;
    float fy = py - y0f;
    float fx = px - x0f;

    int ys[2] = { y0, y0 + 1 };
    int xs[2] = { x0, x0 + 1 };
    float wy[2] = { 1.0f - fy, fy };
    float wx[2] = { 1.0f - fx, fx };

    int   idx[4];
    float w[4];
#pragma unroll
    for (int j = 0; j < 4; j++) {
        int yy = ys[j >> 1];
        int xx = xs[j & 1];
        bool valid = (yy >= 0) && (yy < HH) && (xx >= 0) && (xx < WWW);
        w[j]   = valid ? (wy[j >> 1] * wx[j & 1]) : 0.0f;
        idx[j] = clamp63(yy) * WWW + clamp63(xx);
    }
    g_idx[t] = make_int4(idx[0], idx[1], idx[2], idx[3]);
    g_wgt[t] = make_float4(w[0], w[1], w[2], w[3]);
}

// ---------------------------------------------------------------------------
// Kernel B2: transpose weight [O][C][K2] -> g_Wt [k2][c][o]
// ---------------------------------------------------------------------------
__global__ void transpose_w_kernel(const float* __restrict__ weight) {
    int t = blockIdx.x * blockDim.x + threadIdx.x;   // < K2*C*O
    int o  = t & (OO - 1);
    int ck = t >> 8;
    int c  = ck % CC;
    int k2 = ck / CC;
    g_Wt[t] = weight[((size_t)o * CC + c) * K2C + k2];
}

// ---------------------------------------------------------------------------
// Kernel C: fused gather + SGEMM.
//   Each CTA: 64 pixels x 256 output channels, K = 2304 (k2-major, c-inner).
//   256 threads; warp w handles pixels [p0+8w, p0+8w+8), each lane 8 o's.
// ---------------------------------------------------------------------------
__global__ __launch_bounds__(256, 2)
void dconv_main_kernel(float* __restrict__ out) {
    __shared__ __align__(16) float  sW[16][OO];   // 16 KB: W tile [kc][o]
    __shared__ __align__(16) float  sS[16][64];   //  4 KB: S tile [kc][p]
    __shared__ __align__(16) int4   sIdx[64];
    __shared__ __align__(16) float4 sWb[64];

    int tid  = threadIdx.x;
    int b    = blockIdx.x >> 6;
    int p0   = (blockIdx.x & 63) * 64;
    int lane = tid & 31;
    int warp = tid >> 5;

    int pl = tid & 63;     // producer: pixel within tile
    int g  = tid >> 6;     // producer: channel-subgroup (0..3 -> c offset 4g)

    float acc[8][8];
#pragma unroll
    for (int i = 0; i < 8; i++)
#pragma unroll
        for (int j = 0; j < 8; j++) acc[i][j] = 0.0f;

    const float* xTb = g_xT + (size_t)b * HWSZ * CC;

    for (int k2 = 0; k2 < K2C; k2++) {
        // load bilinear meta for this (b, k2, pixel tile)
        if (tid < 64) {
            size_t mi = ((size_t)(b * K2C + k2) * HWSZ) + p0 + tid;
            sIdx[tid] = g_idx[mi];
            sWb[tid]  = g_wgt[mi];
        }
        for (int c0 = 0; c0 < CC; c0 += 16) {
            __syncthreads();   // meta visible; previous GEMM done reading sS/sW

            // ---- stage S tile: S[ci][p] = sum_j w_j * xT[b][idx_j][c0+ci]
            {
                int4   id = sIdx[pl];
                float4 wv = sWb[pl];
                const float* base = xTb + c0 + g * 4;
                float4 v0 = *(const float4*)(base + (size_t)id.x * CC);
                float4 v1 = *(const float4*)(base + (size_t)id.y * CC);
                float4 v2 = *(const float4*)(base + (size_t)id.z * CC);
                float4 v3 = *(const float4*)(base + (size_t)id.w * CC);
                float s0 = wv.x * v0.x + wv.y * v1.x + wv.z * v2.x + wv.w * v3.x;
                float s1 = wv.x * v0.y + wv.y * v1.y + wv.z * v2.y + wv.w * v3.y;
                float s2 = wv.x * v0.z + wv.y * v1.z + wv.z * v2.z + wv.w * v3.z;
                float s3 = wv.x * v0.w + wv.y * v1.w + wv.z * v2.w + wv.w * v3.w;
                sS[g * 4 + 0][pl] = s0;
                sS[g * 4 + 1][pl] = s1;
                sS[g * 4 + 2][pl] = s2;
                sS[g * 4 + 3][pl] = s3;
            }
            // ---- stage W tile: contiguous 16*256 floats from g_Wt[k2][c0..+16][:]
            {
                const float4* src = (const float4*)(g_Wt + ((size_t)k2 * CC + c0) * OO);
                float4* dst = (float4*)&sW[0][0];
#pragma unroll
                for (int it = 0; it < 4; it++)
                    dst[it * 256 + tid] = src[it * 256 + tid];
            }
            __syncthreads();

            // ---- GEMM on the 16-deep chunk
#pragma unroll
            for (int kk = 0; kk < 16; kk++) {
                float a[8], bb[8];
                *(float4*)&a[0]  = *(const float4*)&sW[kk][lane * 8];
                *(float4*)&a[4]  = *(const float4*)&sW[kk][lane * 8 + 4];
                *(float4*)&bb[0] = *(const float4*)&sS[kk][warp * 8];
                *(float4*)&bb[4] = *(const float4*)&sS[kk][warp * 8 + 4];
#pragma unroll
                for (int i = 0; i < 8; i++)
#pragma unroll
                    for (int j = 0; j < 8; j++)
                        acc[i][j] += a[i] * bb[j];
            }
        }
    }

    // epilogue: out[b][o][p],  o = lane*8 + i,  p = p0 + warp*8 + j
    int pbase = p0 + warp * 8;
#pragma unroll
    for (int i = 0; i < 8; i++) {
        int o = lane * 8 + i;
        float* op = out + ((size_t)b * OO + o) * HWSZ + pbase;
        float4 lo = make_float4(acc[i][0], acc[i][1], acc[i][2], acc[i][3]);
        float4 hi = make_float4(acc[i][4], acc[i][5], acc[i][6], acc[i][7]);
        *(float4*)(op)     = lo;
        *(float4*)(op + 4) = hi;
    }
}

// ---------------------------------------------------------------------------
extern "C" void kernel_launch(void* const* d_in, const int* in_sizes, int n_in,
                              void* d_out, int out_size) {
    const float* x      = (const float*)d_in[0];
    const float* offset = (const float*)d_in[1];
    const float* weight = (const float*)d_in[2];
    float* out = (float*)d_out;

    transpose_x_kernel<<<dim3(HWSZ / 32, CC / 32, BB), dim3(32, 8)>>>(x);
    build_meta_kernel<<<(BB * K2C * HWSZ) / 256, 256>>>(offset);
    transpose_w_kernel<<<(K2C * CC * OO) / 256, 256>>>(weight);
    dconv_main_kernel<<<BB * (HWSZ / 64), 256>>>(out);
}

// round 4
// speedup vs baseline: 1.3719x; 1.3719x over previous
#include <cuda_runtime.h>
#include <cstdint>

// Problem constants
#define BB   8
#define CC   256
#define HH   64
#define WWW  64
#define HWSZ 4096
#define K2C  9
#define OO   256
#define KTOT (K2C * CC)          // 2304
#define CHUNKS (KTOT / 32)       // 72 K-chunks of 32
#define STRD 36                  // smem row stride in floats (32 + 4 pad)

// Scratch (device globals — no allocation allowed)
__device__ float  g_xT[BB * HWSZ * CC];    // x transposed: [B][HW][C]
__device__ float  g_Wk[OO * KTOT];         // weight: [o][k2*256+c], tf32-rounded
__device__ int4   g_idx[BB * K2C * HWSZ];  // 4 clamped corner spatial indices
__device__ float4 g_wgt[BB * K2C * HWSZ];  // 4 bilinear weights (0 if OOB)

__device__ __forceinline__ uint32_t f2tf32(float x) {
    uint32_t r; asm("cvt.rna.tf32.f32 %0, %1;" : "=r"(r) : "f"(x)); return r;
}

// ---------------------------------------------------------------------------
// Kernel A: transpose x [B][C][HW] -> g_xT [B][HW][C]
// ---------------------------------------------------------------------------
__global__ void transpose_x_kernel(const float* __restrict__ x) {
    __shared__ __align__(16) float tile[32][33];
    int b   = blockIdx.z;
    int hw0 = blockIdx.x * 32;
    int c0  = blockIdx.y * 32;
    int tx = threadIdx.x, ty = threadIdx.y;
    const float* xb = x + (size_t)b * CC * HWSZ;
#pragma unroll
    for (int i = 0; i < 4; i++) {
        int c = c0 + ty + i * 8;
        tile[ty + i * 8][tx] = xb[(size_t)c * HWSZ + hw0 + tx];
    }
    __syncthreads();
    float* xt = g_xT + (size_t)b * HWSZ * CC;
#pragma unroll
    for (int i = 0; i < 4; i++) {
        int hw = hw0 + ty + i * 8;
        xt[(size_t)hw * CC + c0 + tx] = tile[tx][ty + i * 8];
    }
}

// ---------------------------------------------------------------------------
// Kernel B: build bilinear meta
// ---------------------------------------------------------------------------
__device__ __forceinline__ int clamp63(int v) { return v < 0 ? 0 : (v > 63 ? 63 : v); }

__global__ void build_meta_kernel(const float* __restrict__ offset) {
    int t = blockIdx.x * blockDim.x + threadIdx.x;
    int p  = t & (HWSZ - 1);
    int bk = t >> 12;
    int k2 = bk % K2C;
    int b  = bk / K2C;
    int ho = p >> 6, wo = p & 63;
    int ky = k2 / 3, kx = k2 % 3;
    const float* ob = offset + (size_t)b * 2 * K2C * HWSZ;
    float dy = ob[(size_t)(k2 * 2 + 0) * HWSZ + p];
    float dx = ob[(size_t)(k2 * 2 + 1) * HWSZ + p];
    float py = (float)(ho - 1 + ky) + dy;
    float px = (float)(wo - 1 + kx) + dx;
    float y0f = floorf(py), x0f = floorf(px);
    int   y0  = (int)y0f,  x0  = (int)x0f;
    float fy = py - y0f,   fx = px - x0f;
    int ys[2] = { y0, y0 + 1 }, xs[2] = { x0, x0 + 1 };
    float wy[2] = { 1.0f - fy, fy }, wx[2] = { 1.0f - fx, fx };
    int idx[4]; float w[4];
#pragma unroll
    for (int j = 0; j < 4; j++) {
        int yy = ys[j >> 1], xx = xs[j & 1];
        bool valid = (yy >= 0) && (yy < HH) && (xx >= 0) && (xx < WWW);
        w[j]   = valid ? (wy[j >> 1] * wx[j & 1]) : 0.0f;
        idx[j] = clamp63(yy) * WWW + clamp63(xx);
    }
    g_idx[t] = make_int4(idx[0], idx[1], idx[2], idx[3]);
    g_wgt[t] = make_float4(w[0], w[1], w[2], w[3]);
}

// ---------------------------------------------------------------------------
// Kernel B2: weight [O][C][K2] -> g_Wk [o][k2*256+c], tf32-rounded
// ---------------------------------------------------------------------------
__global__ void prep_w_kernel(const float* __restrict__ weight) {
    int t = blockIdx.x * blockDim.x + threadIdx.x;   // < OO*KTOT
    int o  = t / KTOT;
    int k  = t - o * KTOT;
    int k2 = k >> 8;
    int c  = k & 255;
    float v = weight[((size_t)o * CC + c) * K2C + k2];
    g_Wk[t] = __uint_as_float(f2tf32(v));
}

// ---------------------------------------------------------------------------
// Kernel C: fused gather + tf32 mma.sync implicit GEMM
//   CTA: 256 threads, tile M=128 (outputs) x N=128 (pixels), K in 72x32 chunks.
//   Warp grid 2x4 -> warp tile 64x32, m16n8k8 tf32 mma.
//   Smem tiles row-padded to 36 floats: all fragment LDS conflict-free.
// ---------------------------------------------------------------------------
__global__ __launch_bounds__(256, 2)
void dconv_mma_kernel(float* __restrict__ out) {
    __shared__ __align__(16) uint32_t A_s[128 * STRD];   // W tile [m][k]
    __shared__ __align__(16) uint32_t B_s[128 * STRD];   // S tile [n][k]
    __shared__ __align__(16) int4   sIdx[128];
    __shared__ __align__(16) float4 sWb[128];

    int tid  = threadIdx.x;
    int lane = tid & 31;
    int wid  = tid >> 5;
    int bx = blockIdx.x;
    int b  = bx >> 6;
    int o0 = ((bx >> 5) & 1) * 128;
    int p0 = (bx & 31) * 128;

    int wm = wid & 1;          // M half: rows [wm*64, +64)
    int wn = wid >> 1;         // N quarter: cols [wn*32, +32)

    // producer roles
    int px    = tid & 127;     // B: pixel in tile
    int bhalf = tid >> 7;      // B: channels [bhalf*16, +16)
    int am    = tid >> 1;      // A: weight row (0..127)
    int ahalf = tid & 1;       // A: channels [ahalf*16, +16)

    float acc[4][4][4];
#pragma unroll
    for (int mi = 0; mi < 4; mi++)
#pragma unroll
        for (int ni = 0; ni < 4; ni++)
#pragma unroll
            for (int r = 0; r < 4; r++) acc[mi][ni][r] = 0.0f;

    const float* xTb  = g_xT + (size_t)b * HWSZ * CC;
    const float* wrow = g_Wk + (size_t)(o0 + am) * KTOT;

    for (int kc = 0; kc < CHUNKS; kc++) {
        int k2 = kc >> 3;
        int c0 = (kc & 7) * 32;

        if ((kc & 7) == 0) {
            if (tid < 128) {
                size_t mi = ((size_t)(b * K2C + k2) * HWSZ) + p0 + tid;
                sIdx[tid] = g_idx[mi];
                sWb[tid]  = g_wgt[mi];
            }
            __syncthreads();
        }

        // ---- gather + combine into registers (B values), weight regs (A)
        uint4 sv[4];
        {
            int4   id = sIdx[px];
            float4 wv = sWb[px];
            const float* gp0 = xTb + (size_t)id.x * CC + c0 + bhalf * 16;
            const float* gp1 = xTb + (size_t)id.y * CC + c0 + bhalf * 16;
            const float* gp2 = xTb + (size_t)id.z * CC + c0 + bhalf * 16;
            const float* gp3 = xTb + (size_t)id.w * CC + c0 + bhalf * 16;
#pragma unroll
            for (int si = 0; si < 4; si++) {
                float4 v0 = *(const float4*)(gp0 + si * 4);
                float4 v1 = *(const float4*)(gp1 + si * 4);
                float4 v2 = *(const float4*)(gp2 + si * 4);
                float4 v3 = *(const float4*)(gp3 + si * 4);
                float r0 = wv.x * v0.x + wv.y * v1.x + wv.z * v2.x + wv.w * v3.x;
                float r1 = wv.x * v0.y + wv.y * v1.y + wv.z * v2.y + wv.w * v3.y;
                float r2 = wv.x * v0.z + wv.y * v1.z + wv.z * v2.z + wv.w * v3.z;
                float r3 = wv.x * v0.w + wv.y * v1.w + wv.z * v2.w + wv.w * v3.w;
                sv[si] = make_uint4(f2tf32(r0), f2tf32(r1), f2tf32(r2), f2tf32(r3));
            }
        }
        uint4 wv4[4];
        {
            const float* wp = wrow + k2 * 256 + c0 + ahalf * 16;
#pragma unroll
            for (int si = 0; si < 4; si++)
                wv4[si] = *(const uint4*)(wp + si * 4);
        }

        __syncthreads();   // previous chunk's MMA done reading smem

        // ---- STS (all 16B-aligned, phase-conflict-free)
#pragma unroll
        for (int si = 0; si < 4; si++)
            *(uint4*)&B_s[px * STRD + bhalf * 16 + si * 4] = sv[si];
#pragma unroll
        for (int si = 0; si < 4; si++)
            *(uint4*)&A_s[am * STRD + ahalf * 16 + si * 4] = wv4[si];

        __syncthreads();

        // ---- MMA phase: 4 k-steps of 8
#pragma unroll
        for (int ks = 0; ks < 4; ks++) {
            int kcol = ks * 8 + (lane & 3);
            uint32_t a[4][4], bfr[4][2];
#pragma unroll
            for (int mi = 0; mi < 4; mi++) {
                int base = (wm * 64 + mi * 16 + (lane >> 2)) * STRD + kcol;
                a[mi][0] = A_s[base];
                a[mi][1] = A_s[base + 8 * STRD];
                a[mi][2] = A_s[base + 4];
                a[mi][3] = A_s[base + 8 * STRD + 4];
            }
#pragma unroll
            for (int ni = 0; ni < 4; ni++) {
                int nb = (wn * 32 + ni * 8 + (lane >> 2)) * STRD + kcol;
                bfr[ni][0] = B_s[nb];
                bfr[ni][1] = B_s[nb + 4];
            }
#pragma unroll
            for (int mi = 0; mi < 4; mi++)
#pragma unroll
                for (int ni = 0; ni < 4; ni++) {
                    asm volatile(
                        "mma.sync.aligned.m16n8k8.row.col.f32.tf32.tf32.f32 "
                        "{%0,%1,%2,%3}, {%4,%5,%6,%7}, {%8,%9}, {%0,%1,%2,%3};"
                        : "+f"(acc[mi][ni][0]), "+f"(acc[mi][ni][1]),
                          "+f"(acc[mi][ni][2]), "+f"(acc[mi][ni][3])
                        : "r"(a[mi][0]), "r"(a[mi][1]), "r"(a[mi][2]), "r"(a[mi][3]),
                          "r"(bfr[ni][0]), "r"(bfr[ni][1]));
                }
        }
    }

    // ---- epilogue: c0,c1 at (row, col..col+1); c2,c3 at (row+8, col..col+1)
    {
        int r  = lane >> 2;
        int cl = (lane & 3) * 2;
#pragma unroll
        for (int mi = 0; mi < 4; mi++) {
            int m = wm * 64 + mi * 16 + r;
            float* op = out + ((size_t)b * OO + (o0 + m)) * HWSZ + p0;
#pragma unroll
            for (int ni = 0; ni < 4; ni++) {
                int n = wn * 32 + ni * 8 + cl;
                *(float2*)(op + n) =
                    make_float2(acc[mi][ni][0], acc[mi][ni][1]);
                *(float2*)(op + 8 * HWSZ + n) =
                    make_float2(acc[mi][ni][2], acc[mi][ni][3]);
            }
        }
    }
}

// ---------------------------------------------------------------------------
extern "C" void kernel_launch(void* const* d_in, const int* in_sizes, int n_in,
                              void* d_out, int out_size) {
    const float* x      = (const float*)d_in[0];
    const float* offset = (const float*)d_in[1];
    const float* weight = (const float*)d_in[2];
    float* out = (float*)d_out;

    transpose_x_kernel<<<dim3(HWSZ / 32, CC / 32, BB), dim3(32, 8)>>>(x);
    build_meta_kernel<<<(BB * K2C * HWSZ) / 256, 256>>>(offset);
    prep_w_kernel<<<(OO * KTOT) / 256, 256>>>(weight);
    dconv_mma_kernel<<<BB * 64, 256>>>(out);
}

// round 5
// speedup vs baseline: 2.2736x; 1.6573x over previous
#include <cuda_runtime.h>
#include <cstdint>

// Problem constants
#define BB   8
#define CC   256
#define HH   64
#define WWW  64
#define HWSZ 4096
#define K2C  9
#define OO   256
#define KTOT (K2C * CC)          // 2304
#define CHUNKS (KTOT / 32)       // 72 K-chunks of 32
#define STRD 36                  // smem row stride in floats (32 + 4 pad)

// Scratch (device globals — no allocation allowed)
__device__ float  g_xT[BB * HWSZ * CC];    // x transposed: [B][HW][C]
__device__ float  g_Wk2[OO * KTOT];        // weight tiled: [ohalf][chunk][row128][k32]
__device__ int4   g_idx[BB * K2C * HWSZ];  // 4 clamped corner spatial indices
__device__ float4 g_wgt[BB * K2C * HWSZ];  // 4 bilinear weights (0 if OOB)

__device__ __forceinline__ uint32_t f2tf32(float x) {
    uint32_t r; asm("cvt.rna.tf32.f32 %0, %1;" : "=r"(r) : "f"(x)); return r;
}

// ---------------------------------------------------------------------------
// Kernel A: transpose x [B][C][HW] -> g_xT [B][HW][C]
// ---------------------------------------------------------------------------
__global__ void transpose_x_kernel(const float* __restrict__ x) {
    __shared__ __align__(16) float tile[32][33];
    int b   = blockIdx.z;
    int hw0 = blockIdx.x * 32;
    int c0  = blockIdx.y * 32;
    int tx = threadIdx.x, ty = threadIdx.y;
    const float* xb = x + (size_t)b * CC * HWSZ;
#pragma unroll
    for (int i = 0; i < 4; i++) {
        int c = c0 + ty + i * 8;
        tile[ty + i * 8][tx] = xb[(size_t)c * HWSZ + hw0 + tx];
    }
    __syncthreads();
    float* xt = g_xT + (size_t)b * HWSZ * CC;
#pragma unroll
    for (int i = 0; i < 4; i++) {
        int hw = hw0 + ty + i * 8;
        xt[(size_t)hw * CC + c0 + tx] = tile[tx][ty + i * 8];
    }
}

// ---------------------------------------------------------------------------
// Kernel B: build bilinear meta
// ---------------------------------------------------------------------------
__device__ __forceinline__ int clamp63(int v) { return v < 0 ? 0 : (v > 63 ? 63 : v); }

__global__ void build_meta_kernel(const float* __restrict__ offset) {
    int t = blockIdx.x * blockDim.x + threadIdx.x;
    int p  = t & (HWSZ - 1);
    int bk = t >> 12;
    int k2 = bk % K2C;
    int b  = bk / K2C;
    int ho = p >> 6, wo = p & 63;
    int ky = k2 / 3, kx = k2 % 3;
    const float* ob = offset + (size_t)b * 2 * K2C * HWSZ;
    float dy = ob[(size_t)(k2 * 2 + 0) * HWSZ + p];
    float dx = ob[(size_t)(k2 * 2 + 1) * HWSZ + p];
    float py = (float)(ho - 1 + ky) + dy;
    float px = (float)(wo - 1 + kx) + dx;
    float y0f = floorf(py), x0f = floorf(px);
    int   y0  = (int)y0f,  x0  = (int)x0f;
    float fy = py - y0f,   fx = px - x0f;
    int ys[2] = { y0, y0 + 1 }, xs[2] = { x0, x0 + 1 };
    float wy[2] = { 1.0f - fy, fy }, wx[2] = { 1.0f - fx, fx };
    int idx[4]; float w[4];
#pragma unroll
    for (int j = 0; j < 4; j++) {
        int yy = ys[j >> 1], xx = xs[j & 1];
        bool valid = (yy >= 0) && (yy < HH) && (xx >= 0) && (xx < WWW);
        w[j]   = valid ? (wy[j >> 1] * wx[j & 1]) : 0.0f;
        idx[j] = clamp63(yy) * WWW + clamp63(xx);
    }
    g_idx[t] = make_int4(idx[0], idx[1], idx[2], idx[3]);
    g_wgt[t] = make_float4(w[0], w[1], w[2], w[3]);
}

// ---------------------------------------------------------------------------
// Kernel B2: weight [O][C][K2] -> g_Wk2 tiled [ohalf][chunk][row][k], tf32
// ---------------------------------------------------------------------------
__global__ void prep_w_kernel(const float* __restrict__ weight) {
    int t = blockIdx.x * blockDim.x + threadIdx.x;   // < OO*KTOT
    int ohalf = t / (CHUNKS * 4096);
    int rem   = t - ohalf * (CHUNKS * 4096);
    int kc  = rem >> 12;
    int f   = rem & 4095;
    int row = f >> 5;
    int kk  = f & 31;
    int o     = ohalf * 128 + row;
    int kglob = kc * 32 + kk;
    int k2 = kglob >> 8;
    int c  = kglob & 255;
    float v = weight[((size_t)o * CC + c) * K2C + k2];
    g_Wk2[t] = __uint_as_float(f2tf32(v));
}

// ---------------------------------------------------------------------------
// Kernel C: fused gather + tf32 mma.sync implicit GEMM
//   CTA: 256 threads, tile M=128 (outputs) x N=128 (pixels), K in 72x32 chunks.
//   Gather: warp-cooperative, lane=channel -> fully coalesced LDG.32.
//   A tile: contiguous 16KB per chunk (pre-tiled weights) -> coalesced LDG.128.
// ---------------------------------------------------------------------------
__global__ __launch_bounds__(256, 2)
void dconv_mma_kernel(float* __restrict__ out) {
    __shared__ __align__(16) uint32_t A_s[128 * STRD];   // W tile [m][k]
    __shared__ __align__(16) uint32_t B_s[128 * STRD];   // S tile [n][k]
    __shared__ __align__(16) int4   sIdx[128];
    __shared__ __align__(16) float4 sWb[128];

    int tid  = threadIdx.x;
    int lane = tid & 31;
    int wid  = tid >> 5;
    int bx = blockIdx.x;
    int b  = bx >> 6;
    int ohalf = (bx >> 5) & 1;
    int o0 = ohalf * 128;
    int p0 = (bx & 31) * 128;

    int wm = wid & 1;          // M half: rows [wm*64, +64)
    int wn = wid >> 1;         // N quarter: cols [wn*32, +32)

    float acc[4][4][4];
#pragma unroll
    for (int mi = 0; mi < 4; mi++)
#pragma unroll
        for (int ni = 0; ni < 4; ni++)
#pragma unroll
            for (int r = 0; r < 4; r++) acc[mi][ni][r] = 0.0f;

    const float* xTb = g_xT + (size_t)b * HWSZ * CC;
    const float* wbase = g_Wk2 + (size_t)ohalf * CHUNKS * 4096 + tid * 16;

    for (int kc = 0; kc < CHUNKS; kc++) {
        int c0 = (kc & 7) * 32;

        if ((kc & 7) == 0) {
            int k2 = kc >> 3;
            __syncthreads();   // everyone done reading previous meta
            if (tid < 128) {
                size_t mi = ((size_t)(b * K2C + k2) * HWSZ) + p0 + tid;
                sIdx[tid] = g_idx[mi];
                sWb[tid]  = g_wgt[mi];
            }
            __syncthreads();
        }

        // ---- coalesced gather: warp w -> pixels [w*16, w*16+16), lane=channel
        float sreg[16];
        {
            const float* xc = xTb + c0 + lane;
#pragma unroll
            for (int q = 0; q < 16; q++) {
                int p = wid * 16 + q;
                int4   id = sIdx[p];
                float4 wv = sWb[p];
                float v0 = xc[(size_t)id.x * CC];
                float v1 = xc[(size_t)id.y * CC];
                float v2 = xc[(size_t)id.z * CC];
                float v3 = xc[(size_t)id.w * CC];
                sreg[q] = wv.x * v0 + wv.y * v1 + wv.z * v2 + wv.w * v3;
            }
        }
        // ---- A chunk: contiguous 16KB, thread t -> floats [t*16, t*16+16)
        uint4 wv4[4];
        {
            const float* wp = wbase + (size_t)kc * 4096;
#pragma unroll
            for (int si = 0; si < 4; si++)
                wv4[si] = *(const uint4*)(wp + si * 4);
        }

        __syncthreads();   // previous chunk's MMA done reading smem

        // ---- STS
#pragma unroll
        for (int q = 0; q < 16; q++)
            B_s[(wid * 16 + q) * STRD + lane] = f2tf32(sreg[q]);
        {
            int arow  = tid >> 1;
            int ahalf = tid & 1;
#pragma unroll
            for (int si = 0; si < 4; si++)
                *(uint4*)&A_s[arow * STRD + ahalf * 16 + si * 4] = wv4[si];
        }

        __syncthreads();

        // ---- MMA phase: 4 k-steps of 8
#pragma unroll
        for (int ks = 0; ks < 4; ks++) {
            int kcol = ks * 8 + (lane & 3);
            uint32_t a[4][4], bfr[4][2];
#pragma unroll
            for (int mi = 0; mi < 4; mi++) {
                int base = (wm * 64 + mi * 16 + (lane >> 2)) * STRD + kcol;
                a[mi][0] = A_s[base];
                a[mi][1] = A_s[base + 8 * STRD];
                a[mi][2] = A_s[base + 4];
                a[mi][3] = A_s[base + 8 * STRD + 4];
            }
#pragma unroll
            for (int ni = 0; ni < 4; ni++) {
                int nb = (wn * 32 + ni * 8 + (lane >> 2)) * STRD + kcol;
                bfr[ni][0] = B_s[nb];
                bfr[ni][1] = B_s[nb + 4];
            }
#pragma unroll
            for (int mi = 0; mi < 4; mi++)
#pragma unroll
                for (int ni = 0; ni < 4; ni++) {
                    asm volatile(
                        "mma.sync.aligned.m16n8k8.row.col.f32.tf32.tf32.f32 "
                        "{%0,%1,%2,%3}, {%4,%5,%6,%7}, {%8,%9}, {%0,%1,%2,%3};"
                        : "+f"(acc[mi][ni][0]), "+f"(acc[mi][ni][1]),
                          "+f"(acc[mi][ni][2]), "+f"(acc[mi][ni][3])
                        : "r"(a[mi][0]), "r"(a[mi][1]), "r"(a[mi][2]), "r"(a[mi][3]),
                          "r"(bfr[ni][0]), "r"(bfr[ni][1]));
                }
        }
    }

    // ---- epilogue
    {
        int r  = lane >> 2;
        int cl = (lane & 3) * 2;
#pragma unroll
        for (int mi = 0; mi < 4; mi++) {
            int m = wm * 64 + mi * 16 + r;
            float* op = out + ((size_t)b * OO + (o0 + m)) * HWSZ + p0;
#pragma unroll
            for (int ni = 0; ni < 4; ni++) {
                int n = wn * 32 + ni * 8 + cl;
                *(float2*)(op + n) =
                    make_float2(acc[mi][ni][0], acc[mi][ni][1]);
                *(float2*)(op + 8 * HWSZ + n) =
                    make_float2(acc[mi][ni][2], acc[mi][ni][3]);
            }
        }
    }
}

// ---------------------------------------------------------------------------
extern "C" void kernel_launch(void* const* d_in, const int* in_sizes, int n_in,
                              void* d_out, int out_size) {
    const float* x      = (const float*)d_in[0];
    const float* offset = (const float*)d_in[1];
    const float* weight = (const float*)d_in[2];
    float* out = (float*)d_out;

    transpose_x_kernel<<<dim3(HWSZ / 32, CC / 32, BB), dim3(32, 8)>>>(x);
    build_meta_kernel<<<(BB * K2C * HWSZ) / 256, 256>>>(offset);
    prep_w_kernel<<<(OO * KTOT) / 256, 256>>>(weight);
    dconv_mma_kernel<<<BB * 64, 256>>>(out);
}

// round 6
// speedup vs baseline: 2.7678x; 1.2174x over previous
#include <cuda_runtime.h>
#include <cstdint>

// Problem constants
#define BB   8
#define CC   256
#define HH   64
#define WWW  64
#define HWSZ 4096
#define K2C  9
#define OO   256
#define KTOT (K2C * CC)          // 2304
#define CHUNKS (KTOT / 32)       // 72 K-chunks of 32
#define STRD 40                  // B smem row stride in floats

// Scratch (device globals — no allocation allowed)
__device__ float  g_xT[BB * HWSZ * CC];    // x transposed: [B][HW][C]
__device__ float  g_WkF[OO * KTOT];        // weights in mma-fragment order
__device__ int4   g_idx[BB * K2C * HWSZ];  // 4 clamped corner spatial indices
__device__ float4 g_wgt[BB * K2C * HWSZ];  // 4 bilinear weights (0 if OOB)

__device__ __forceinline__ uint32_t f2tf32(float x) {
    uint32_t r; asm("cvt.rna.tf32.f32 %0, %1;" : "=r"(r) : "f"(x)); return r;
}

// ---------------------------------------------------------------------------
// Kernel A: transpose x [B][C][HW] -> g_xT [B][HW][C]
// ---------------------------------------------------------------------------
__global__ void transpose_x_kernel(const float* __restrict__ x) {
    __shared__ __align__(16) float tile[32][33];
    int b   = blockIdx.z;
    int hw0 = blockIdx.x * 32;
    int c0  = blockIdx.y * 32;
    int tx = threadIdx.x, ty = threadIdx.y;
    const float* xb = x + (size_t)b * CC * HWSZ;
#pragma unroll
    for (int i = 0; i < 4; i++) {
        int c = c0 + ty + i * 8;
        tile[ty + i * 8][tx] = xb[(size_t)c * HWSZ + hw0 + tx];
    }
    __syncthreads();
    float* xt = g_xT + (size_t)b * HWSZ * CC;
#pragma unroll
    for (int i = 0; i < 4; i++) {
        int hw = hw0 + ty + i * 8;
        xt[(size_t)hw * CC + c0 + tx] = tile[tx][ty + i * 8];
    }
}

// ---------------------------------------------------------------------------
// Kernel B: build bilinear meta
// ---------------------------------------------------------------------------
__device__ __forceinline__ int clamp63(int v) { return v < 0 ? 0 : (v > 63 ? 63 : v); }

__global__ void build_meta_kernel(const float* __restrict__ offset) {
    int t = blockIdx.x * blockDim.x + threadIdx.x;
    int p  = t & (HWSZ - 1);
    int bk = t >> 12;
    int k2 = bk % K2C;
    int b  = bk / K2C;
    int ho = p >> 6, wo = p & 63;
    int ky = k2 / 3, kx = k2 % 3;
    const float* ob = offset + (size_t)b * 2 * K2C * HWSZ;
    float dy = ob[(size_t)(k2 * 2 + 0) * HWSZ + p];
    float dx = ob[(size_t)(k2 * 2 + 1) * HWSZ + p];
    float py = (float)(ho - 1 + ky) + dy;
    float px = (float)(wo - 1 + kx) + dx;
    float y0f = floorf(py), x0f = floorf(px);
    int   y0  = (int)y0f,  x0  = (int)x0f;
    float fy = py - y0f,   fx = px - x0f;
    int ys[2] = { y0, y0 + 1 }, xs[2] = { x0, x0 + 1 };
    float wy[2] = { 1.0f - fy, fy }, wx[2] = { 1.0f - fx, fx };
    int idx[4]; float w[4];
#pragma unroll
    for (int j = 0; j < 4; j++) {
        int yy = ys[j >> 1], xx = xs[j & 1];
        bool valid = (yy >= 0) && (yy < HH) && (xx >= 0) && (xx < WWW);
        w[j]   = valid ? (wy[j >> 1] * wx[j & 1]) : 0.0f;
        idx[j] = clamp63(yy) * WWW + clamp63(xx);
    }
    g_idx[t] = make_int4(idx[0], idx[1], idx[2], idx[3]);
    g_wgt[t] = make_float4(w[0], w[1], w[2], w[3]);
}

// ---------------------------------------------------------------------------
// Kernel B2: weight -> g_WkF in mma fragment order, tf32-rounded.
//   Layout: [ohalf][wm][kc] blocks of 2048 floats;
//   block idx = ((mi*4+ks)*32 + lane)*4 + e, where e: 0=(r,k) 1=(r+8,k)
//   2=(r,k+4) 3=(r+8,k+4); r = wm*64+mi*16+(lane>>2), k = ks*8+(lane&3).
// ---------------------------------------------------------------------------
__global__ void prep_w_kernel(const float* __restrict__ weight) {
    int t = blockIdx.x * blockDim.x + threadIdx.x;   // < OO*KTOT
    int e    = t & 3;
    int r1   = t >> 2;
    int lane = r1 & 31;
    int m4k  = (r1 >> 5) & 15;
    int r2   = r1 >> 9;              // (ohalf*2+wm)*72 + kc
    int kc   = r2 % CHUNKS;
    int half = r2 / CHUNKS;          // ohalf*2 + wm
    int wm = half & 1, ohalf = half >> 1;
    int mi = m4k >> 2, ks = m4k & 3;
    int row = wm * 64 + mi * 16 + (lane >> 2) + (e & 1) * 8;
    int kin = ks * 8 + (lane & 3) + (e >> 1) * 4;
    int o  = ohalf * 128 + row;
    int kg = kc * 32 + kin;
    int k2 = kg >> 8, c = kg & 255;
    float v = weight[((size_t)o * CC + c) * K2C + k2];
    g_WkF[t] = __uint_as_float(f2tf32(v));
}

// ---------------------------------------------------------------------------
// Kernel C: fused gather + tf32 mma.sync implicit GEMM, pipelined.
//   B double-buffered in smem (k-permuted, STRD=40); A fragments LDG'd
//   directly from pre-permuted gmem (L2-resident, reused by 32 CTAs).
// ---------------------------------------------------------------------------
__global__ __launch_bounds__(256, 2)
void dconv_mma_kernel(float* __restrict__ out) {
    __shared__ __align__(16) uint32_t B_s[2][128 * STRD];
    __shared__ __align__(16) int4   sIdx[2][128];
    __shared__ __align__(16) float4 sWb[2][128];

    int tid  = threadIdx.x;
    int lane = tid & 31;
    int wid  = tid >> 5;
    int bx = blockIdx.x;
    int b  = bx >> 6;
    int ohalf = (bx >> 5) & 1;
    int o0 = ohalf * 128;
    int p0 = (bx & 31) * 128;

    int wm = wid & 1;          // M half: rows [wm*64, +64)
    int wn = wid >> 1;         // N quarter: cols [wn*32, +32)

    float acc[4][4][4];
#pragma unroll
    for (int mi = 0; mi < 4; mi++)
#pragma unroll
        for (int ni = 0; ni < 4; ni++)
#pragma unroll
            for (int r = 0; r < 4; r++) acc[mi][ni][r] = 0.0f;

    const float* xTb = g_xT + (size_t)b * HWSZ * CC;
    const float* wfh = g_WkF + (size_t)(ohalf * 2 + wm) * CHUNKS * 2048;
    // permuted B column for producer lane (lane = k within chunk)
    int cperm = (lane & 24) + ((lane & 3) << 1) + ((lane >> 2) & 1);

    // ---- prologue: meta for k2=0, gather chunk 0
    if (tid < 128) {
        size_t mi0 = ((size_t)(b * K2C) * HWSZ) + p0 + tid;
        sIdx[0][tid] = g_idx[mi0];
        sWb[0][tid]  = g_wgt[mi0];
    }
    __syncthreads();
    float sreg[16];
    {
        const float* xc = xTb + lane;
#pragma unroll
        for (int q = 0; q < 16; q++) {
            int p = wid * 16 + q;
            int4   id = sIdx[0][p];
            float4 wv = sWb[0][p];
            sreg[q] = wv.x * xc[(size_t)id.x * CC] + wv.y * xc[(size_t)id.y * CC]
                    + wv.z * xc[(size_t)id.z * CC] + wv.w * xc[(size_t)id.w * CC];
        }
#pragma unroll
        for (int q = 0; q < 16; q++)
            B_s[0][(wid * 16 + q) * STRD + cperm] = f2tf32(sreg[q]);
    }

    for (int kc = 0; kc < CHUNKS; kc++) {
        __syncthreads();          // B_s[kc&1] ready; all MMA(kc-1) done
        int nkc = kc + 1;
        if (nkc < CHUNKS && (nkc & 7) == 0) {
            int nk2 = nkc >> 3;
            if (tid < 128) {
                size_t mi0 = ((size_t)(b * K2C + nk2) * HWSZ) + p0 + tid;
                sIdx[nk2 & 1][tid] = g_idx[mi0];
                sWb[nk2 & 1][tid]  = g_wgt[mi0];
            }
            __syncthreads();
        }

        // ---- gather chunk kc+1 into registers (overlaps MMA below)
        if (nkc < CHUNKS) {
            int k2g = nkc >> 3;
            int mb  = k2g & 1;
            int c0  = (nkc & 7) * 32;
            const float* xc = xTb + c0 + lane;
#pragma unroll
            for (int q = 0; q < 16; q++) {
                int p = wid * 16 + q;
                int4   id = sIdx[mb][p];
                float4 wv = sWb[mb][p];
                sreg[q] = wv.x * xc[(size_t)id.x * CC] + wv.y * xc[(size_t)id.y * CC]
                        + wv.z * xc[(size_t)id.z * CC] + wv.w * xc[(size_t)id.w * CC];
            }
        }

        // ---- MMA on chunk kc: A fragments straight from gmem
        {
            const float* wkc = wfh + (size_t)kc * 2048;
            const uint32_t* Bb = &B_s[kc & 1][0];
#pragma unroll
            for (int ks = 0; ks < 4; ks++) {
                uint4 afr[4];
#pragma unroll
                for (int mi = 0; mi < 4; mi++)
                    afr[mi] = *(const uint4*)(wkc + ((mi * 4 + ks) * 32 + lane) * 4);
                uint32_t bfr[4][2];
#pragma unroll
                for (int ni = 0; ni < 4; ni++) {
                    int nrow = wn * 32 + ni * 8 + (lane >> 2);
                    float2 bv = *(const float2*)(Bb + nrow * STRD + ks * 8 + 2 * (lane & 3));
                    bfr[ni][0] = __float_as_uint(bv.x);
                    bfr[ni][1] = __float_as_uint(bv.y);
                }
#pragma unroll
                for (int mi = 0; mi < 4; mi++)
#pragma unroll
                    for (int ni = 0; ni < 4; ni++) {
                        asm volatile(
                            "mma.sync.aligned.m16n8k8.row.col.f32.tf32.tf32.f32 "
                            "{%0,%1,%2,%3}, {%4,%5,%6,%7}, {%8,%9}, {%0,%1,%2,%3};"
                            : "+f"(acc[mi][ni][0]), "+f"(acc[mi][ni][1]),
                              "+f"(acc[mi][ni][2]), "+f"(acc[mi][ni][3])
                            : "r"(afr[mi].x), "r"(afr[mi].y), "r"(afr[mi].z), "r"(afr[mi].w),
                              "r"(bfr[ni][0]), "r"(bfr[ni][1]));
                    }
            }
        }

        // ---- stage gathered chunk kc+1 (other buffer; racers all past top sync)
        if (nkc < CHUNKS) {
#pragma unroll
            for (int q = 0; q < 16; q++)
                B_s[nkc & 1][(wid * 16 + q) * STRD + cperm] = f2tf32(sreg[q]);
        }
    }

    // ---- epilogue
    {
        int r  = lane >> 2;
        int cl = (lane & 3) * 2;
#pragma unroll
        for (int mi = 0; mi < 4; mi++) {
            int m = wm * 64 + mi * 16 + r;
            float* op = out + ((size_t)b * OO + (o0 + m)) * HWSZ + p0;
#pragma unroll
            for (int ni = 0; ni < 4; ni++) {
                int n = wn * 32 + ni * 8 + cl;
                *(float2*)(op + n) =
                    make_float2(acc[mi][ni][0], acc[mi][ni][1]);
                *(float2*)(op + 8 * HWSZ + n) =
                    make_float2(acc[mi][ni][2], acc[mi][ni][3]);
            }
        }
    }
}

// ---------------------------------------------------------------------------
extern "C" void kernel_launch(void* const* d_in, const int* in_sizes, int n_in,
                              void* d_out, int out_size) {
    const float* x      = (const float*)d_in[0];
    const float* offset = (const float*)d_in[1];
    const float* weight = (const float*)d_in[2];
    float* out = (float*)d_out;

    transpose_x_kernel<<<dim3(HWSZ / 32, CC / 32, BB), dim3(32, 8)>>>(x);
    build_meta_kernel<<<(BB * K2C * HWSZ) / 256, 256>>>(offset);
    prep_w_kernel<<<(OO * KTOT) / 256, 256>>>(weight);
    dconv_mma_kernel<<<BB * 64, 256>>>(out);
}

// round 7
// speedup vs baseline: 4.4851x; 1.6204x over previous
#include <cuda_runtime.h>
#include <cuda_fp16.h>
#include <cstdint>

// Problem constants
#define BB   8
#define CC   256
#define HH   64
#define WWW  64
#define HWSZ 4096
#define K2C  9
#define OO   256
#define KTOT (K2C * CC)          // 2304
#define NKB  (KTOT / 64)         // 36 slabs of K=64
#define SW   36                  // B smem row stride in words (72 fp16)

// Scratch (device globals — no allocation allowed)
__device__ float    g_xT[BB * HWSZ * CC];     // x transposed: [B][HW][C]
__device__ uint32_t g_WkFH[OO * KTOT / 2];    // weights fp16x2, mma-fragment order
__device__ int4     g_idx[BB * K2C * HWSZ];   // 4 clamped corner spatial indices
__device__ float4   g_wgt[BB * K2C * HWSZ];   // 4 bilinear weights (0 if OOB)

// ---------------------------------------------------------------------------
// Kernel A: transpose x [B][C][HW] -> g_xT [B][HW][C]
// ---------------------------------------------------------------------------
__global__ void transpose_x_kernel(const float* __restrict__ x) {
    __shared__ __align__(16) float tile[32][33];
    int b   = blockIdx.z;
    int hw0 = blockIdx.x * 32;
    int c0  = blockIdx.y * 32;
    int tx = threadIdx.x, ty = threadIdx.y;
    const float* xb = x + (size_t)b * CC * HWSZ;
#pragma unroll
    for (int i = 0; i < 4; i++) {
        int c = c0 + ty + i * 8;
        tile[ty + i * 8][tx] = xb[(size_t)c * HWSZ + hw0 + tx];
    }
    __syncthreads();
    float* xt = g_xT + (size_t)b * HWSZ * CC;
#pragma unroll
    for (int i = 0; i < 4; i++) {
        int hw = hw0 + ty + i * 8;
        xt[(size_t)hw * CC + c0 + tx] = tile[tx][ty + i * 8];
    }
}

// ---------------------------------------------------------------------------
// Kernel B: build bilinear meta
// ---------------------------------------------------------------------------
__device__ __forceinline__ int clamp63(int v) { return v < 0 ? 0 : (v > 63 ? 63 : v); }

__global__ void build_meta_kernel(const float* __restrict__ offset) {
    int t = blockIdx.x * blockDim.x + threadIdx.x;
    int p  = t & (HWSZ - 1);
    int bk = t >> 12;
    int k2 = bk % K2C;
    int b  = bk / K2C;
    int ho = p >> 6, wo = p & 63;
    int ky = k2 / 3, kx = k2 % 3;
    const float* ob = offset + (size_t)b * 2 * K2C * HWSZ;
    float dy = ob[(size_t)(k2 * 2 + 0) * HWSZ + p];
    float dx = ob[(size_t)(k2 * 2 + 1) * HWSZ + p];
    float py = (float)(ho - 1 + ky) + dy;
    float px = (float)(wo - 1 + kx) + dx;
    float y0f = floorf(py), x0f = floorf(px);
    int   y0  = (int)y0f,  x0  = (int)x0f;
    float fy = py - y0f,   fx = px - x0f;
    int ys[2] = { y0, y0 + 1 }, xs[2] = { x0, x0 + 1 };
    float wy[2] = { 1.0f - fy, fy }, wx[2] = { 1.0f - fx, fx };
    int idx[4]; float w[4];
#pragma unroll
    for (int j = 0; j < 4; j++) {
        int yy = ys[j >> 1], xx = xs[j & 1];
        bool valid = (yy >= 0) && (yy < HH) && (xx >= 0) && (xx < WWW);
        w[j]   = valid ? (wy[j >> 1] * wx[j & 1]) : 0.0f;
        idx[j] = clamp63(yy) * WWW + clamp63(xx);
    }
    g_idx[t] = make_int4(idx[0], idx[1], idx[2], idx[3]);
    g_wgt[t] = make_float4(w[0], w[1], w[2], w[3]);
}

// ---------------------------------------------------------------------------
// Kernel B2: weight -> g_WkFH fp16x2 in m16n8k16 fragment order.
//   t = ((((half*36 + kb)*4 + mi)*4 + ks)*32 + lane)*4 + e
//   half = ohalf*2 + wm;  row = wm*64+mi*16+(lane>>2)+(e&1)*8
//   k = kb*64 + ks*16 + (e>>1)*8 + 2*(lane&3)  (fp16x2 covers k, k+1)
// ---------------------------------------------------------------------------
__global__ void prep_w_kernel(const float* __restrict__ weight) {
    int t = blockIdx.x * blockDim.x + threadIdx.x;   // < OO*KTOT/2
    int e    = t & 3;
    int lane = (t >> 2) & 31;
    int ks   = (t >> 7) & 3;
    int mi   = (t >> 9) & 3;
    int kb   = (t >> 11) % NKB;
    int half = (t >> 11) / NKB;
    int wm = half & 1, ohalf = half >> 1;
    int row = wm * 64 + mi * 16 + (lane >> 2) + (e & 1) * 8;
    int kg  = kb * 64 + ks * 16 + (e >> 1) * 8 + 2 * (lane & 3);
    int o  = ohalf * 128 + row;
    int k2 = kg >> 8, c = kg & 255;
    float w0 = weight[((size_t)o * CC + c) * K2C + k2];
    float w1 = weight[((size_t)o * CC + c + 1) * K2C + k2];
    __half2 h = __floats2half2_rn(w0, w1);
    g_WkFH[t] = *(const uint32_t*)&h;
}

// ---------------------------------------------------------------------------
// Kernel C: fused gather + fp16 m16n8k16 mma implicit GEMM, pipelined.
//   36 slabs of K=64. B double-buffered fp16 smem (row stride 72 fp16);
//   A fragments LDG'd from fragment-ordered gmem (L2-resident).
// ---------------------------------------------------------------------------
__global__ __launch_bounds__(256, 2)
void dconv_mma_kernel(float* __restrict__ out) {
    __shared__ __align__(16) uint32_t B_s[2][128 * SW];   // fp16x2 words
    __shared__ __align__(16) int4   sIdx[2][128];
    __shared__ __align__(16) float4 sWb[2][128];

    int tid  = threadIdx.x;
    int lane = tid & 31;
    int wid  = tid >> 5;
    int bx = blockIdx.x;
    int b  = bx >> 6;
    int ohalf = (bx >> 5) & 1;
    int o0 = ohalf * 128;
    int p0 = (bx & 31) * 128;

    int wm = wid & 1;          // M half: rows [wm*64, +64)
    int wn = wid >> 1;         // N quarter: cols [wn*32, +32)

    float acc[4][4][4];
#pragma unroll
    for (int mi = 0; mi < 4; mi++)
#pragma unroll
        for (int ni = 0; ni < 4; ni++)
#pragma unroll
            for (int r = 0; r < 4; r++) acc[mi][ni][r] = 0.0f;

    const float* xTb = g_xT + (size_t)b * HWSZ * CC;
    const uint4* wfh = (const uint4*)(g_WkFH + (size_t)(ohalf * 2 + wm) * NKB * 2048);

    uint32_t hreg[16];

    // ---- prologue: meta for k2=0, gather slab 0
    if (tid < 128) {
        size_t mi0 = ((size_t)(b * K2C) * HWSZ) + p0 + tid;
        sIdx[0][tid] = g_idx[mi0];
        sWb[0][tid]  = g_wgt[mi0];
    }
    __syncthreads();
    {
        const float* xc = xTb + 2 * lane;
#pragma unroll
        for (int q = 0; q < 16; q++) {
            int p = wid * 16 + q;
            int4   id = sIdx[0][p];
            float4 wv = sWb[0][p];
            float2 u0 = *(const float2*)(xc + (size_t)id.x * CC);
            float2 u1 = *(const float2*)(xc + (size_t)id.y * CC);
            float2 u2 = *(const float2*)(xc + (size_t)id.z * CC);
            float2 u3 = *(const float2*)(xc + (size_t)id.w * CC);
            float rx = wv.x * u0.x + wv.y * u1.x + wv.z * u2.x + wv.w * u3.x;
            float ry = wv.x * u0.y + wv.y * u1.y + wv.z * u2.y + wv.w * u3.y;
            __half2 h = __floats2half2_rn(rx, ry);
            hreg[q] = *(const uint32_t*)&h;
        }
#pragma unroll
        for (int q = 0; q < 16; q++)
            B_s[0][(wid * 16 + q) * SW + lane] = hreg[q];
    }

    for (int kb = 0; kb < NKB; kb++) {
        __syncthreads();          // B_s[kb&1] ready; all MMA(kb-1) done
        int nkb = kb + 1;
        if (nkb < NKB && (nkb & 3) == 0) {
            int nk2 = nkb >> 2;
            if (tid < 128) {
                size_t mi0 = ((size_t)(b * K2C + nk2) * HWSZ) + p0 + tid;
                sIdx[nk2 & 1][tid] = g_idx[mi0];
                sWb[nk2 & 1][tid]  = g_wgt[mi0];
            }
            __syncthreads();
        }

        // ---- gather slab kb+1 into registers (overlaps MMA below)
        if (nkb < NKB) {
            int mb = (nkb >> 2) & 1;
            int c0 = (nkb & 3) * 64;
            const float* xc = xTb + c0 + 2 * lane;
#pragma unroll
            for (int q = 0; q < 16; q++) {
                int p = wid * 16 + q;
                int4   id = sIdx[mb][p];
                float4 wv = sWb[mb][p];
                float2 u0 = *(const float2*)(xc + (size_t)id.x * CC);
                float2 u1 = *(const float2*)(xc + (size_t)id.y * CC);
                float2 u2 = *(const float2*)(xc + (size_t)id.z * CC);
                float2 u3 = *(const float2*)(xc + (size_t)id.w * CC);
                float rx = wv.x * u0.x + wv.y * u1.x + wv.z * u2.x + wv.w * u3.x;
                float ry = wv.x * u0.y + wv.y * u1.y + wv.z * u2.y + wv.w * u3.y;
                __half2 h = __floats2half2_rn(rx, ry);
                hreg[q] = *(const uint32_t*)&h;
            }
        }

        // ---- MMA on slab kb: 4 k-steps of 16
        {
            const uint4* wkc = wfh + (size_t)kb * 512;     // 512 uint4 per slab
            const uint32_t* Bb = &B_s[kb & 1][0];
#pragma unroll
            for (int ks = 0; ks < 4; ks++) {
                uint4 afr[4];
#pragma unroll
                for (int mi = 0; mi < 4; mi++)
                    afr[mi] = wkc[(mi * 4 + ks) * 32 + lane];
                uint32_t bfr[4][2];
#pragma unroll
                for (int ni = 0; ni < 4; ni++) {
                    int base = (wn * 32 + ni * 8 + (lane >> 2)) * SW + ks * 8 + (lane & 3);
                    bfr[ni][0] = Bb[base];
                    bfr[ni][1] = Bb[base + 4];
                }
#pragma unroll
                for (int mi = 0; mi < 4; mi++)
#pragma unroll
                    for (int ni = 0; ni < 4; ni++) {
                        asm volatile(
                            "mma.sync.aligned.m16n8k16.row.col.f32.f16.f16.f32 "
                            "{%0,%1,%2,%3}, {%4,%5,%6,%7}, {%8,%9}, {%0,%1,%2,%3};"
                            : "+f"(acc[mi][ni][0]), "+f"(acc[mi][ni][1]),
                              "+f"(acc[mi][ni][2]), "+f"(acc[mi][ni][3])
                            : "r"(afr[mi].x), "r"(afr[mi].y), "r"(afr[mi].z), "r"(afr[mi].w),
                              "r"(bfr[ni][0]), "r"(bfr[ni][1]));
                    }
            }
        }

        // ---- stage gathered slab kb+1 (other buffer)
        if (nkb < NKB) {
#pragma unroll
            for (int q = 0; q < 16; q++)
                B_s[nkb & 1][(wid * 16 + q) * SW + lane] = hreg[q];
        }
    }

    // ---- epilogue
    {
        int r  = lane >> 2;
        int cl = (lane & 3) * 2;
#pragma unroll
        for (int mi = 0; mi < 4; mi++) {
            int m = wm * 64 + mi * 16 + r;
            float* op = out + ((size_t)b * OO + (o0 + m)) * HWSZ + p0;
#pragma unroll
            for (int ni = 0; ni < 4; ni++) {
                int n = wn * 32 + ni * 8 + cl;
                *(float2*)(op + n) =
                    make_float2(acc[mi][ni][0], acc[mi][ni][1]);
                *(float2*)(op + 8 * HWSZ + n) =
                    make_float2(acc[mi][ni][2], acc[mi][ni][3]);
            }
        }
    }
}

// ---------------------------------------------------------------------------
extern "C" void kernel_launch(void* const* d_in, const int* in_sizes, int n_in,
                              void* d_out, int out_size) {
    const float* x      = (const float*)d_in[0];
    const float* offset = (const float*)d_in[1];
    const float* weight = (const float*)d_in[2];
    float* out = (float*)d_out;

    transpose_x_kernel<<<dim3(HWSZ / 32, CC / 32, BB), dim3(32, 8)>>>(x);
    build_meta_kernel<<<(BB * K2C * HWSZ) / 256, 256>>>(offset);
    prep_w_kernel<<<(OO * KTOT / 2) / 256, 256>>>(weight);
    dconv_mma_kernel<<<BB * 64, 256>>>(out);
}